// round 1
// baseline (speedup 1.0000x reference)
#include <cuda_runtime.h>
#include <cstdint>

#define B_   4096
#define XD   128
#define YD   64
#define T_   200
#define LAT  100
#define G3   300
#define CH   50
#define R_   32
#define NB   (B_ / R_)     // 128 blocks
#define NT   256

// SMEM layout (float offsets)
#define OFF_WHH 0          // [100][300]          30000
#define OFF_BIH 30000      // [300]
#define OFF_BHH 30300      // [300]
#define OFF_BL1 30600      // [100]
#define OFF_BL2 30700      // [64]
#define OFF_H   30764      // [100][36]  (stride 36, [k][r])   3600
#define OFF_AX  34364      // [128][32]  ([k][r])              4096
#define OFF_YP  38460      // [64][33]   ([d][r])              2112
#define OFF_GX  40572      // [32][304]  ([r][j])              9728
#define OFF_GHN 50300      // [32][104]  ([r][j])              3328
#define OFF_O1  53628      // [100][36]  ([k][r])              3600
#define SMEM_FLOATS 57228  // 228912 bytes

__device__ __forceinline__ float fsig(float x) {
    return __fdividef(1.0f, 1.0f + __expf(-x));
}
__device__ __forceinline__ float ftanh_(float x) {
    float e = __expf(2.0f * x);
    return 1.0f - __fdividef(2.0f, e + 1.0f);
}

// [4 rows r0..r0+3] x [4 cols j0..j0+3] register-tile GEMM.
// A in SMEM as [k][r] (lda stride), W in GMEM row-major [K][ldw].
__device__ __forceinline__ void gemm_small(
    const float* __restrict__ smem, int aoff, int lda,
    const float* __restrict__ W, int ldw, int K,
    int j0, int r0, float acc[4][4])
{
#pragma unroll
    for (int i = 0; i < 4; i++)
#pragma unroll
        for (int c = 0; c < 4; c++) acc[i][c] = 0.f;
#pragma unroll 4
    for (int k = 0; k < K; k++) {
        const float4 a = *(const float4*)&smem[aoff + k * lda + r0];
        const float av[4] = {a.x, a.y, a.z, a.w};
        const float4 wv = __ldg((const float4*)(W + k * ldw + j0));
        const float wc[4] = {wv.x, wv.y, wv.z, wv.w};
#pragma unroll
        for (int i = 0; i < 4; i++)
#pragma unroll
            for (int c = 0; c < 4; c++)
                acc[i][c] = fmaf(av[i], wc[c], acc[i][c]);
    }
}

extern "C" __global__ void __launch_bounds__(NT, 1) gru_kernel(
    const float* __restrict__ x, const float* __restrict__ y, const void* __restrict__ ymask,
    const float* __restrict__ Wmu1, const float* __restrict__ bmu1,
    const float* __restrict__ Wmu2, const float* __restrict__ bmu2,
    const float* __restrict__ Wih, const float* __restrict__ bih,
    const float* __restrict__ Whh, const float* __restrict__ bhh,
    const float* __restrict__ Wl1, const float* __restrict__ bl1,
    const float* __restrict__ Wl2, const float* __restrict__ bl2,
    const float* __restrict__ Wc1, const float* __restrict__ bc1,
    const float* __restrict__ Wc2, const float* __restrict__ bc2,
    float* __restrict__ out, int has_cls)
{
    extern __shared__ float sm[];
    const int tid  = threadIdx.x;
    const int lane = tid & 31;
    const int w    = tid >> 5;
    const int r0   = w << 2;          // row quad base (8 warps x 4 rows = 32)
    const int b0   = blockIdx.x * R_;

    // ---- stage Whh + biases into SMEM; zero y_prev ----
    for (int i = tid; i < (LAT * G3) / 4; i += NT)
        ((float4*)(sm + OFF_WHH))[i] = __ldg(((const float4*)Whh) + i);
    for (int i = tid; i < G3; i += NT) { sm[OFF_BIH + i] = bih[i]; sm[OFF_BHH + i] = bhh[i]; }
    for (int i = tid; i < LAT; i += NT) sm[OFF_BL1 + i] = bl1[i];
    for (int i = tid; i < YD;  i += NT) sm[OFF_BL2 + i] = bl2[i];
    for (int i = tid; i < YD * 33; i += NT) sm[OFF_YP + i] = 0.f;

    // ---- mask dtype detection (uint8 / int32 / float32), deterministic ----
    const unsigned word = ((const unsigned*)ymask)[tid];   // first 1024 bytes
    const int big = __syncthreads_or((word & 0xFEFEFEFEu) != 0u);  // any byte > 1 -> f32
    const int odd = __syncthreads_or((word & 0xFFFFFF00u) != 0u);  // bytes 1..3 set -> u8
    const int mode = big ? 2 : (odd ? 0 : 1);              // 0=u8, 1=i32, 2=f32

    // ---- stage x into ax ([k][r]) ----
    for (int e = tid; e < R_ * XD; e += NT) {
        const int r = e & 31, k = e >> 5;
        sm[OFF_AX + k * 32 + r] = __ldg(&x[(size_t)(b0 + r) * XD + k]);
    }
    __syncthreads();

    // ---- h0 = tanh(x @ Wmu1 + bmu1) @ Wmu2 + bmu2 ----
    if (lane < 25) {
        float acc[4][4];
        gemm_small(sm, OFF_AX, 32, Wmu1, LAT, XD, lane * 4, r0, acc);
        const float4 bb = __ldg((const float4*)&bmu1[lane * 4]);
        const float bc[4] = {bb.x, bb.y, bb.z, bb.w};
#pragma unroll
        for (int i = 0; i < 4; i++)
#pragma unroll
            for (int c = 0; c < 4; c++)
                sm[OFF_O1 + (lane * 4 + c) * 36 + r0 + i] = ftanh_(acc[i][c] + bc[c]);
    }
    __syncthreads();
    if (lane < 25) {
        float acc[4][4];
        gemm_small(sm, OFF_O1, 36, Wmu2, LAT, LAT, lane * 4, r0, acc);
        const float4 bb = __ldg((const float4*)&bmu2[lane * 4]);
        const float bc[4] = {bb.x, bb.y, bb.z, bb.w};
#pragma unroll
        for (int i = 0; i < 4; i++)
#pragma unroll
            for (int c = 0; c < 4; c++)
                sm[OFF_H + (lane * 4 + c) * 36 + r0 + i] = acc[i][c] + bc[c];
    }

    // ---- prefetch y/mask for t=0 ----
    float yv[8], mfv[8];
    auto preload = [&](int t) {
#pragma unroll
        for (int i = 0; i < 8; i++) {
            const int e = tid + NT * i;
            const int r = e & 31, d = e >> 5;
            const size_t off = (size_t)(b0 + r) * (YD * T_) + (size_t)d * T_ + t;
            yv[i] = __ldg(&y[off]);
            float m;
            if (mode == 0)      m = (((const unsigned char*)ymask)[off] != 0) ? 1.f : 0.f;
            else if (mode == 1) m = (((const int*)ymask)[off] != 0) ? 1.f : 0.f;
            else                m = (((const float*)ymask)[off] != 0.f) ? 1.f : 0.f;
            mfv[i] = m;
        }
    };
    preload(0);
    __syncthreads();

    // ================= main recurrence =================
    for (int t = 0; t < T_; ++t) {
        // -- combine teacher forcing -> ax ([k][r], k interleaved value/mask) --
#pragma unroll
        for (int i = 0; i < 8; i++) {
            const int e = tid + NT * i;
            const int r = e & 31, d = e >> 5;
            const float m  = mfv[i];
            const float yp = sm[OFF_YP + d * 33 + r];
            const float yin = (m != 0.f) ? yv[i] : yp;
            sm[OFF_AX + (2 * d) * 32 + r]     = yin;
            sm[OFF_AX + (2 * d + 1) * 32 + r] = m;
        }
        if (t + 1 < T_) preload(t + 1);   // hide next step's y/mask latency
        __syncthreads();

        // -- GEMM1: gx = ax[32x128] @ Wih[128x300] -> gx_s --
        {
            float acc[3][4][4];
#pragma unroll
            for (int cc = 0; cc < 3; cc++)
#pragma unroll
                for (int i = 0; i < 4; i++)
#pragma unroll
                    for (int c = 0; c < 4; c++) acc[cc][i][c] = 0.f;
#pragma unroll 4
            for (int k = 0; k < XD; k++) {
                const float4 a = *(const float4*)&sm[OFF_AX + k * 32 + r0];
                const float av[4] = {a.x, a.y, a.z, a.w};
#pragma unroll
                for (int cc = 0; cc < 3; cc++) {
                    if (cc < 2 || lane < 11) {
                        const float4 wv = __ldg((const float4*)&Wih[k * G3 + lane * 4 + cc * 128]);
                        const float wc[4] = {wv.x, wv.y, wv.z, wv.w};
#pragma unroll
                        for (int i = 0; i < 4; i++)
#pragma unroll
                            for (int c = 0; c < 4; c++)
                                acc[cc][i][c] = fmaf(av[i], wc[c], acc[cc][i][c]);
                    }
                }
            }
#pragma unroll
            for (int cc = 0; cc < 3; cc++)
                if (cc < 2 || lane < 11) {
                    const int j0 = lane * 4 + cc * 128;
#pragma unroll
                    for (int i = 0; i < 4; i++) {
                        float4 f = make_float4(acc[cc][i][0], acc[cc][i][1], acc[cc][i][2], acc[cc][i][3]);
                        *(float4*)&sm[OFF_GX + (r0 + i) * 304 + j0] = f;
                    }
                }
        }
        // no barrier: GEMM2 read-modify-writes only its OWN gx elements

        // -- GEMM2: gh = h[32x100] @ Whh_s[100x300]; r,z parts += gx, n part -> ghn --
        {
            float acc[3][4][4];
#pragma unroll
            for (int cc = 0; cc < 3; cc++)
#pragma unroll
                for (int i = 0; i < 4; i++)
#pragma unroll
                    for (int c = 0; c < 4; c++) acc[cc][i][c] = 0.f;
#pragma unroll 4
            for (int k = 0; k < LAT; k++) {
                const float4 a = *(const float4*)&sm[OFF_H + k * 36 + r0];
                const float av[4] = {a.x, a.y, a.z, a.w};
#pragma unroll
                for (int cc = 0; cc < 3; cc++) {
                    if (cc < 2 || lane < 11) {
                        const float4 wv = *(const float4*)&sm[OFF_WHH + k * G3 + lane * 4 + cc * 128];
                        const float wc[4] = {wv.x, wv.y, wv.z, wv.w};
#pragma unroll
                        for (int i = 0; i < 4; i++)
#pragma unroll
                            for (int c = 0; c < 4; c++)
                                acc[cc][i][c] = fmaf(av[i], wc[c], acc[cc][i][c]);
                    }
                }
            }
#pragma unroll
            for (int cc = 0; cc < 3; cc++)
                if (cc < 2 || lane < 11) {
                    const int j0 = lane * 4 + cc * 128;
#pragma unroll
                    for (int i = 0; i < 4; i++) {
                        if (j0 < 200) {
                            float4 g = *(float4*)&sm[OFF_GX + (r0 + i) * 304 + j0];
                            g.x += acc[cc][i][0]; g.y += acc[cc][i][1];
                            g.z += acc[cc][i][2]; g.w += acc[cc][i][3];
                            *(float4*)&sm[OFF_GX + (r0 + i) * 304 + j0] = g;
                        } else {
                            float4 f = make_float4(acc[cc][i][0], acc[cc][i][1], acc[cc][i][2], acc[cc][i][3]);
                            *(float4*)&sm[OFF_GHN + (r0 + i) * 104 + (j0 - 200)] = f;
                        }
                    }
                }
        }
        __syncthreads();

        // -- gates: r,z = sigmoid; n = tanh(gxn + r*ghn); h = (1-z)*n + z*h --
#pragma unroll
        for (int it = 0; it < 13; ++it) {
            const int idx = tid + NT * it;
            if (idx < R_ * LAT) {
                const int r = idx / LAT;
                const int j = idx - r * LAT;
                const float g_r = sm[OFF_GX + r * 304 + j]       + sm[OFF_BIH + j]       + sm[OFF_BHH + j];
                const float g_z = sm[OFF_GX + r * 304 + 100 + j] + sm[OFF_BIH + 100 + j] + sm[OFF_BHH + 100 + j];
                const float gxn = sm[OFF_GX + r * 304 + 200 + j] + sm[OFF_BIH + 200 + j];
                const float ghn = sm[OFF_GHN + r * 104 + j]      + sm[OFF_BHH + 200 + j];
                const float rg = fsig(g_r);
                const float z  = fsig(g_z);
                const float n  = ftanh_(gxn + rg * ghn);
                const float hd = sm[OFF_H + j * 36 + r];
                sm[OFF_H + j * 36 + r] = (1.f - z) * n + z * hd;
            }
        }
        __syncthreads();

        // -- GEMM3: o1 = tanh(h @ Wl1 + bl1) --
        if (lane < 25) {
            float acc[4][4];
            gemm_small(sm, OFF_H, 36, Wl1, LAT, LAT, lane * 4, r0, acc);
            const float4 bb = *(const float4*)&sm[OFF_BL1 + lane * 4];
            const float bc[4] = {bb.x, bb.y, bb.z, bb.w};
#pragma unroll
            for (int i = 0; i < 4; i++)
#pragma unroll
                for (int c = 0; c < 4; c++)
                    sm[OFF_O1 + (lane * 4 + c) * 36 + r0 + i] = ftanh_(acc[i][c] + bc[c]);
        }
        __syncthreads();

        // -- GEMM4: out_t = o1 @ Wl2 + bl2; write output + y_prev --
        if (lane < 16) {
            float acc[4][4];
            gemm_small(sm, OFF_O1, 36, Wl2, YD, LAT, lane * 4, r0, acc);
            const float4 bb = *(const float4*)&sm[OFF_BL2 + lane * 4];
            const float bc[4] = {bb.x, bb.y, bb.z, bb.w};
#pragma unroll
            for (int i = 0; i < 4; i++)
#pragma unroll
                for (int c = 0; c < 4; c++) {
                    const float v = acc[i][c] + bc[c];
                    const int d = lane * 4 + c, rr = r0 + i;
                    out[(size_t)(b0 + rr) * (YD * T_) + (size_t)d * T_ + t] = v;
                    sm[OFF_YP + d * 33 + rr] = v;
                }
        }
        __syncthreads();
    }

    // ---- classifier: sigmoid(relu(h_T @ Wc1 + bc1) @ Wc2 + bc2) ----
    if (has_cls) {
        for (int idx = tid; idx < R_ * CH; idx += NT) {
            const int r = idx & 31, c = idx >> 5;
            float acc = __ldg(&bc1[c]);
            for (int k = 0; k < LAT; k++)
                acc = fmaf(sm[OFF_H + k * 36 + r], __ldg(&Wc1[k * CH + c]), acc);
            sm[OFF_O1 + c * 36 + r] = fmaxf(acc, 0.f);
        }
        __syncthreads();
        if (tid < R_) {
            float acc = __ldg(&bc2[0]);
            for (int c = 0; c < CH; c++)
                acc = fmaf(sm[OFF_O1 + c * 36 + tid], __ldg(&Wc2[c]), acc);
            out[(size_t)B_ * YD * T_ + b0 + tid] = fsig(acc);
        }
    }
}

extern "C" void kernel_launch(void* const* d_in, const int* in_sizes, int n_in,
                              void* d_out, int out_size)
{
    cudaFuncSetAttribute(gru_kernel, cudaFuncAttributeMaxDynamicSharedMemorySize,
                         SMEM_FLOATS * (int)sizeof(float));
    const int has_cls = (out_size > B_ * YD * T_) ? 1 : 0;
    gru_kernel<<<NB, NT, SMEM_FLOATS * sizeof(float)>>>(
        (const float*)d_in[0],   // x
        (const float*)d_in[1],   // y
        d_in[2],                 // y_mask (dtype auto-detected)
        (const float*)d_in[3],  (const float*)d_in[4],   // Wmu1, bmu1
        (const float*)d_in[5],  (const float*)d_in[6],   // Wmu2, bmu2
        (const float*)d_in[11], (const float*)d_in[12],  // Wih, bih
        (const float*)d_in[13], (const float*)d_in[14],  // Whh, bhh
        (const float*)d_in[15], (const float*)d_in[16],  // Wl1, bl1
        (const float*)d_in[17], (const float*)d_in[18],  // Wl2, bl2
        (const float*)d_in[19], (const float*)d_in[20],  // Wc1, bc1
        (const float*)d_in[21], (const float*)d_in[22],  // Wc2, bc2
        (float*)d_out, has_cls);
}